// round 10
// baseline (speedup 1.0000x reference)
#include <cuda_runtime.h>
#include <cstdint>

// Problem constants
#define L_TOT      1200000
#define D_IN       64
#define D_ENC      128
#define N_CLS      10
#define JWIN       30
#define ROWS_PB    480                 // 16 segments, 30 m16-tiles per block
#define SEG_PB     16
#define NBLOCKS    (L_TOT / ROWS_PB)   // 2500
#define THREADS    256
#define CHUNK_ROWS 32                  // 2 m-tiles per chunk (1 per m-group)
#define NCHUNK     (ROWS_PB / CHUNK_ROWS)   // 15
#define PF_VEC     ((CHUNK_ROWS * D_IN / 4) / THREADS)   // 2 float4 per thread

// Permuted smem layout: xs[row][q*QP + t] = tf32(x[row][q + 4*t]), q=0..3, t=0..15
//  -> each lane's A-fragment elements (fixed q) are contiguous: LDS.128 loads.
//  QP=20 (16 payload + 4 pad), RS=80 -> LDS.128 phases tile all 32 banks.
#define QP         20
#define RS         80
#define BUF_FLOATS (CHUNK_ROWS * RS)              // 2560
#define F_STRIDE   136
#define FT_FLOATS  (2 * SEG_PB * F_STRIDE)        // 4352 (two m-group planes)
#define SMEM_FLOATS (2 * BUF_FLOATS + FT_FLOATS)  // 9472
#define SMEM_BYTES (SMEM_FLOATS * 4)              // 37888

__device__ __forceinline__ uint32_t f2tf32(float f) {
    uint32_t u;
    asm("cvt.rna.tf32.f32 %0, %1;" : "=r"(u) : "f"(f));
    return u;
}

__device__ __forceinline__ void mma_tf32(float c[4],
                                         uint32_t a0, uint32_t a1, uint32_t a2, uint32_t a3,
                                         uint32_t b0, uint32_t b1) {
    asm volatile(
        "mma.sync.aligned.m16n8k8.row.col.f32.tf32.tf32.f32 "
        "{%0,%1,%2,%3}, {%4,%5,%6,%7}, {%8,%9}, {%0,%1,%2,%3};"
        : "+f"(c[0]), "+f"(c[1]), "+f"(c[2]), "+f"(c[3])
        : "r"(a0), "r"(a1), "r"(a2), "r"(a3), "r"(b0), "r"(b1));
}

__device__ __forceinline__ float warp8_reduce(float v) {
    v += __shfl_xor_sync(0xffffffffu, v, 4);
    v += __shfl_xor_sync(0xffffffffu, v, 8);
    v += __shfl_xor_sync(0xffffffffu, v, 16);
    return v;
}

__global__ __launch_bounds__(THREADS, 2)
void classifier_kernel(const float* __restrict__ x,
                       const float* __restrict__ Wloc,
                       const float* __restrict__ W,
                       float* __restrict__ out) {
    extern __shared__ float smem[];
    float* bufs  = smem;                          // 2 x [32][80] tf32-bits
    float* feats = smem + 2 * BUF_FLOATS;         // [2][16][136] fp32 partials

    const int tid = threadIdx.x;
    const int blk = blockIdx.x;
    const long rowBase = (long)blk * ROWS_PB;

    // staging slots: i = j*256 + tid -> row i/16 (j adds 16 rows), float4-col i%16
    const int pr0 = tid >> 4;
    const int pc4 = tid & 15;

    // ---- prologue: LDG chunk 0 (start DRAM immediately) ----
    float4 pf[PF_VEC];
    {
        const float4* s4 = reinterpret_cast<const float4*>(x + rowBase * D_IN);
        #pragma unroll
        for (int j = 0; j < PF_VEC; ++j)
            pf[j] = s4[j * THREADS + tid];
    }

    // ---- overlap: zero feats, preload B fragments ----
    for (int i = tid; i < FT_FLOATS; i += THREADS) feats[i] = 0.0f;

    const int lane  = tid & 31;
    const int wid   = tid >> 5;
    const int g     = wid & 1;           // m-group: tile g of each chunk
    const int strip = wid >> 1;          // 4 n-strips of 32 cols
    const int nb    = strip * 32;
    const int r     = lane >> 2;
    const int q     = lane & 3;

    // B frag (m16n8k8, col): n = nb + f*8 + r, k = ks*8 + q (+4 for b1)
    uint32_t bq[8][4][2];
    {
        const float* wb = Wloc + (nb + r) * D_IN + q;
        #pragma unroll
        for (int ks = 0; ks < 8; ++ks) {
            #pragma unroll
            for (int f = 0; f < 4; ++f) {
                bq[ks][f][0] = f2tf32(__ldg(wb + f * 8 * D_IN + ks * 8));
                bq[ks][f][1] = f2tf32(__ldg(wb + f * 8 * D_IN + ks * 8 + 4));
            }
        }
    }

    // ---- stage chunk 0 (convert + permute scatter) ----
    #pragma unroll
    for (int j = 0; j < PF_VEC; ++j) {
        float* b0 = bufs + (pr0 + j * 16) * RS + pc4;
        b0[0 * QP] = __uint_as_float(f2tf32(pf[j].x));
        b0[1 * QP] = __uint_as_float(f2tf32(pf[j].y));
        b0[2 * QP] = __uint_as_float(f2tf32(pf[j].z));
        b0[3 * QP] = __uint_as_float(f2tf32(pf[j].w));
    }
    __syncthreads();

    float* fg = feats + g * SEG_PB * F_STRIDE;    // this m-group's partial plane

    // ---- pipelined mainloop over 15 chunks ----
    for (int c = 0; c < NCHUNK; ++c) {
        if (c + 1 < NCHUNK) {
            const float4* s4 = reinterpret_cast<const float4*>(
                x + (rowBase + (long)(c + 1) * CHUNK_ROWS) * D_IN);
            #pragma unroll
            for (int j = 0; j < PF_VEC; ++j)
                pf[j] = s4[j * THREADS + tid];
        }

        const float* xs = bufs + (c & 1) * BUF_FLOATS;

        // this warp's single m-tile in the chunk: rows g*16 .. g*16+15
        float acc[4][4];
        #pragma unroll
        for (int f = 0; f < 4; ++f)
            acc[f][0] = acc[f][1] = acc[f][2] = acc[f][3] = 0.0f;

        const uint4* lo4 = reinterpret_cast<const uint4*>(
            xs + (g * 16 + r) * RS + q * QP);
        const uint4* hi4 = reinterpret_cast<const uint4*>(
            xs + (g * 16 + r + 8) * RS + q * QP);

        #pragma unroll
        for (int j = 0; j < 4; ++j) {
            uint4 lo = lo4[j];          // t=4j..4j+3: ks=2j (x=a0,y=a2), ks=2j+1 (z=a0,w=a2)
            uint4 hi = hi4[j];
            #pragma unroll
            for (int f = 0; f < 4; ++f)
                mma_tf32(acc[f], lo.x, hi.x, lo.y, hi.y,
                         bq[2 * j][f][0], bq[2 * j][f][1]);
            #pragma unroll
            for (int f = 0; f < 4; ++f)
                mma_tf32(acc[f], lo.z, hi.z, lo.w, hi.w,
                         bq[2 * j + 1][f][0], bq[2 * j + 1][f][1]);
        }

        // relu
        #pragma unroll
        for (int f = 0; f < 4; ++f) {
            acc[f][0] = fmaxf(acc[f][0], 0.0f);
            acc[f][1] = fmaxf(acc[f][1], 0.0f);
            acc[f][2] = fmaxf(acc[f][2], 0.0f);
            acc[f][3] = fmaxf(acc[f][3], 0.0f);
        }

        // segment pooling (at most one boundary per 16-row tile)
        const int rA  = c * CHUNK_ROWS + g * 16;
        const int sLo = rA / JWIN;
        const int sHi = (rA + 15) / JWIN;

        if (sLo == sHi) {
            float sum[8];
            #pragma unroll
            for (int f = 0; f < 4; ++f) {
                sum[2 * f]     = acc[f][0] + acc[f][2];
                sum[2 * f + 1] = acc[f][1] + acc[f][3];
            }
            #pragma unroll
            for (int t = 0; t < 8; ++t) sum[t] = warp8_reduce(sum[t]);
            if (lane < 4) {
                #pragma unroll
                for (int f = 0; f < 4; ++f) {
                    fg[sLo * F_STRIDE + nb + f * 8 + 2 * lane]     += sum[2 * f];
                    fg[sLo * F_STRIDE + nb + f * 8 + 2 * lane + 1] += sum[2 * f + 1];
                }
            }
        } else {
            const int b = sHi * JWIN - rA;
            const bool pL = (r < b);
            const bool pH = (r + 8 < b);
            float lo[8], hi[8];
            #pragma unroll
            for (int f = 0; f < 4; ++f) {
                float l0 = pL ? acc[f][0] : 0.0f;
                float l1 = pL ? acc[f][1] : 0.0f;
                float l2 = pH ? acc[f][2] : 0.0f;
                float l3 = pH ? acc[f][3] : 0.0f;
                lo[2 * f]     = l0 + l2;
                lo[2 * f + 1] = l1 + l3;
                hi[2 * f]     = (acc[f][0] + acc[f][2]) - lo[2 * f];
                hi[2 * f + 1] = (acc[f][1] + acc[f][3]) - lo[2 * f + 1];
            }
            #pragma unroll
            for (int t = 0; t < 8; ++t) { lo[t] = warp8_reduce(lo[t]); hi[t] = warp8_reduce(hi[t]); }
            if (lane < 4) {
                #pragma unroll
                for (int f = 0; f < 4; ++f) {
                    fg[sLo * F_STRIDE + nb + f * 8 + 2 * lane]     += lo[2 * f];
                    fg[sLo * F_STRIDE + nb + f * 8 + 2 * lane + 1] += lo[2 * f + 1];
                    fg[sHi * F_STRIDE + nb + f * 8 + 2 * lane]     += hi[2 * f];
                    fg[sHi * F_STRIDE + nb + f * 8 + 2 * lane + 1] += hi[2 * f + 1];
                }
            }
        }

        // stage chunk c+1 into the other buffer (its prior readers finished
        // at the barrier ending iteration c-1)
        if (c + 1 < NCHUNK) {
            float* nx = bufs + ((c + 1) & 1) * BUF_FLOATS;
            #pragma unroll
            for (int j = 0; j < PF_VEC; ++j) {
                float* b0 = nx + (pr0 + j * 16) * RS + pc4;
                b0[0 * QP] = __uint_as_float(f2tf32(pf[j].x));
                b0[1 * QP] = __uint_as_float(f2tf32(pf[j].y));
                b0[2 * QP] = __uint_as_float(f2tf32(pf[j].z));
                b0[3 * QP] = __uint_as_float(f2tf32(pf[j].w));
            }
        }
        __syncthreads();
    }

    // ---- fused classifier: out[s][cc] = (1/30) * sum_e (f0[e]+f1[e]) * W[cc][e] ----
    if (tid < SEG_PB * N_CLS) {
        const int s  = tid / N_CLS;
        const int cc = tid % N_CLS;
        const float* f0 = feats + s * F_STRIDE;
        const float* f1 = feats + (SEG_PB + s) * F_STRIDE;
        const float* wr = W + cc * D_ENC;
        float sum = 0.0f;
        #pragma unroll 8
        for (int e = 0; e < D_ENC; ++e)
            sum += (f0[e] + f1[e]) * __ldg(wr + e);
        out[((long)blk * SEG_PB + s) * N_CLS + cc] = sum * (1.0f / (float)JWIN);
    }
}

extern "C" void kernel_launch(void* const* d_in, const int* in_sizes, int n_in,
                              void* d_out, int out_size) {
    const float* x    = (const float*)d_in[0];   // [1200000, 64]
    const float* Wloc = (const float*)d_in[1];   // [128, 64]
    const float* W    = (const float*)d_in[2];   // [10, 128]
    float* out = (float*)d_out;                  // [40000, 10]

    cudaFuncSetAttribute(classifier_kernel,
                         cudaFuncAttributeMaxDynamicSharedMemorySize, SMEM_BYTES);
    classifier_kernel<<<NBLOCKS, THREADS, SMEM_BYTES>>>(x, Wloc, W, out);
}

// round 11
// speedup vs baseline: 1.2288x; 1.2288x over previous
#include <cuda_runtime.h>
#include <cstdint>

// Problem constants
#define L_TOT      1200000
#define D_IN       64
#define D_ENC      128
#define N_CLS      10
#define JWIN       30
#define ROWS_PB    480                 // 16 segments, 30 m16-tiles per block
#define SEG_PB     16
#define NBLOCKS    (L_TOT / ROWS_PB)   // 2500
#define THREADS    256
#define CHUNK_ROWS 32                  // 2 m-tiles per chunk (1 per m-group)
#define NCHUNK     (ROWS_PB / CHUNK_ROWS)   // 15
#define PF_VEC     ((CHUNK_ROWS * D_IN / 4) / THREADS)   // 2 float4 per thread

// Permuted smem layout: xs[row][q*QP + t] = tf32(x[row][q + 4*t]), q=0..3, t=0..15
//  -> each lane's A-fragment elements (fixed q) are contiguous: LDS.128 loads.
//  QP=20 (16 payload + 4 pad), RS=80 -> LDS.128 phases tile all 32 banks.
#define QP         20
#define RS         80
#define BUF_FLOATS (CHUNK_ROWS * RS)              // 2560
#define F_STRIDE   136
#define FT_FLOATS  (2 * SEG_PB * F_STRIDE)        // 4352 (two m-group planes)
#define SMEM_FLOATS (2 * BUF_FLOATS + FT_FLOATS)  // 9472
#define SMEM_BYTES (SMEM_FLOATS * 4)              // 37888

__device__ __forceinline__ uint32_t f2tf32(float f) {
    uint32_t u;
    asm("cvt.rna.tf32.f32 %0, %1;" : "=r"(u) : "f"(f));
    return u;
}

__device__ __forceinline__ void mma_tf32(float c[4],
                                         uint32_t a0, uint32_t a1, uint32_t a2, uint32_t a3,
                                         uint32_t b0, uint32_t b1) {
    asm volatile(
        "mma.sync.aligned.m16n8k8.row.col.f32.tf32.tf32.f32 "
        "{%0,%1,%2,%3}, {%4,%5,%6,%7}, {%8,%9}, {%0,%1,%2,%3};"
        : "+f"(c[0]), "+f"(c[1]), "+f"(c[2]), "+f"(c[3])
        : "r"(a0), "r"(a1), "r"(a2), "r"(a3), "r"(b0), "r"(b1));
}

// Reduce-scatter of 8 values across the 8-lane group {lane ^ 4,8,16}.
// Returns this lane's total for value index j = 4*b2 + 2*b3 + b4
// (b2=(lane>>2)&1, b3=(lane>>3)&1, b4=(lane>>4)&1). 7 shfl + 7 add.
__device__ __forceinline__ float rs8(const float v[8], int lane) {
    float w[4];
    #pragma unroll
    for (int i = 0; i < 4; ++i) {
        float give = (lane & 4) ? v[i] : v[4 + i];
        float keep = (lane & 4) ? v[4 + i] : v[i];
        w[i] = keep + __shfl_xor_sync(0xffffffffu, give, 4);
    }
    float u[2];
    #pragma unroll
    for (int i = 0; i < 2; ++i) {
        float give = (lane & 8) ? w[i] : w[2 + i];
        float keep = (lane & 8) ? w[2 + i] : w[i];
        u[i] = keep + __shfl_xor_sync(0xffffffffu, give, 8);
    }
    float give = (lane & 16) ? u[0] : u[1];
    float keep = (lane & 16) ? u[1] : u[0];
    return keep + __shfl_xor_sync(0xffffffffu, give, 16);
}

__global__ __launch_bounds__(THREADS, 2)
void classifier_kernel(const float* __restrict__ x,
                       const float* __restrict__ Wloc,
                       const float* __restrict__ W,
                       float* __restrict__ out) {
    extern __shared__ float smem[];
    float* bufs  = smem;                          // 2 x [32][80] tf32-bits
    float* feats = smem + 2 * BUF_FLOATS;         // [2][16][136] fp32 partials

    const int tid = threadIdx.x;
    const int blk = blockIdx.x;
    const long rowBase = (long)blk * ROWS_PB;

    // staging slots: i = j*256 + tid -> row i/16 (j adds 16 rows), float4-col i%16
    const int pr0 = tid >> 4;
    const int pc4 = tid & 15;

    // ---- prologue: LDG chunk 0 (start DRAM immediately) ----
    float4 pf[PF_VEC];
    {
        const float4* s4 = reinterpret_cast<const float4*>(x + rowBase * D_IN);
        #pragma unroll
        for (int j = 0; j < PF_VEC; ++j)
            pf[j] = s4[j * THREADS + tid];
    }

    // ---- overlap: zero feats, preload B fragments ----
    for (int i = tid; i < FT_FLOATS; i += THREADS) feats[i] = 0.0f;

    const int lane  = tid & 31;
    const int wid   = tid >> 5;
    const int g     = wid & 1;           // m-group: tile g of each chunk
    const int strip = wid >> 1;          // 4 n-strips of 32 cols
    const int nb    = strip * 32;
    const int r     = lane >> 2;
    const int q     = lane & 3;

    // reduce-scatter output column for this lane within the warp's 32-col strip
    const int colIdx = nb
        + (2 * ((lane >> 2) & 1) + ((lane >> 3) & 1)) * 8   // f = 2*b2 + b3
        + 2 * q
        + ((lane >> 4) & 1);                                // p = b4

    // B frag (m16n8k8, col): n = nb + f*8 + r, k = ks*8 + q (+4 for b1)
    uint32_t bq[8][4][2];
    {
        const float* wb = Wloc + (nb + r) * D_IN + q;
        #pragma unroll
        for (int ks = 0; ks < 8; ++ks) {
            #pragma unroll
            for (int f = 0; f < 4; ++f) {
                bq[ks][f][0] = f2tf32(__ldg(wb + f * 8 * D_IN + ks * 8));
                bq[ks][f][1] = f2tf32(__ldg(wb + f * 8 * D_IN + ks * 8 + 4));
            }
        }
    }

    // ---- stage chunk 0 (convert + permute scatter) ----
    #pragma unroll
    for (int j = 0; j < PF_VEC; ++j) {
        float* b0 = bufs + (pr0 + j * 16) * RS + pc4;
        b0[0 * QP] = __uint_as_float(f2tf32(pf[j].x));
        b0[1 * QP] = __uint_as_float(f2tf32(pf[j].y));
        b0[2 * QP] = __uint_as_float(f2tf32(pf[j].z));
        b0[3 * QP] = __uint_as_float(f2tf32(pf[j].w));
    }
    __syncthreads();

    float* fg = feats + g * SEG_PB * F_STRIDE;    // this m-group's partial plane

    // ---- pipelined mainloop over 15 chunks (fully unrolled: boundary tests
    //      and segment indices fold to compile-time constants) ----
    #pragma unroll
    for (int c = 0; c < NCHUNK; ++c) {
        if (c + 1 < NCHUNK) {
            const float4* s4 = reinterpret_cast<const float4*>(
                x + (rowBase + (long)(c + 1) * CHUNK_ROWS) * D_IN);
            #pragma unroll
            for (int j = 0; j < PF_VEC; ++j)
                pf[j] = s4[j * THREADS + tid];
        }

        const float* xs = bufs + (c & 1) * BUF_FLOATS;

        // this warp's single m-tile in the chunk: rows g*16 .. g*16+15
        float acc[4][4];
        #pragma unroll
        for (int f = 0; f < 4; ++f)
            acc[f][0] = acc[f][1] = acc[f][2] = acc[f][3] = 0.0f;

        const uint4* lo4 = reinterpret_cast<const uint4*>(
            xs + (g * 16 + r) * RS + q * QP);
        const uint4* hi4 = reinterpret_cast<const uint4*>(
            xs + (g * 16 + r + 8) * RS + q * QP);

        #pragma unroll
        for (int j = 0; j < 4; ++j) {
            uint4 lo = lo4[j];          // t=4j..4j+3: ks=2j (x=a0,y=a2), ks=2j+1 (z=a0,w=a2)
            uint4 hi = hi4[j];
            #pragma unroll
            for (int f = 0; f < 4; ++f)
                mma_tf32(acc[f], lo.x, hi.x, lo.y, hi.y,
                         bq[2 * j][f][0], bq[2 * j][f][1]);
            #pragma unroll
            for (int f = 0; f < 4; ++f)
                mma_tf32(acc[f], lo.z, hi.z, lo.w, hi.w,
                         bq[2 * j + 1][f][0], bq[2 * j + 1][f][1]);
        }

        // relu
        #pragma unroll
        for (int f = 0; f < 4; ++f) {
            acc[f][0] = fmaxf(acc[f][0], 0.0f);
            acc[f][1] = fmaxf(acc[f][1], 0.0f);
            acc[f][2] = fmaxf(acc[f][2], 0.0f);
            acc[f][3] = fmaxf(acc[f][3], 0.0f);
        }

        // segment pooling via reduce-scatter (constants after unroll)
        const int rA  = c * CHUNK_ROWS + g * 16;
        const int sLo = rA / JWIN;
        const int sHi = (rA + 15) / JWIN;

        if (sLo == sHi) {
            // whole tile in one segment: 8 column sums, 7 shfl
            float v[8];
            #pragma unroll
            for (int f = 0; f < 4; ++f) {
                v[2 * f]     = acc[f][0] + acc[f][2];
                v[2 * f + 1] = acc[f][1] + acc[f][3];
            }
            float s = rs8(v, lane);
            fg[sLo * F_STRIDE + colIdx] += s;     // 32 distinct cols, conflict-free
        } else {
            // tile spans a boundary at local row b: split rows, two reduce-scatters
            const int b = sHi * JWIN - rA;
            const bool pL = (r < b);
            const bool pH = (r + 8 < b);
            float vlo[8], vhi[8];
            #pragma unroll
            for (int f = 0; f < 4; ++f) {
                float l0 = pL ? acc[f][0] : 0.0f;
                float l1 = pL ? acc[f][1] : 0.0f;
                float l2 = pH ? acc[f][2] : 0.0f;
                float l3 = pH ? acc[f][3] : 0.0f;
                vlo[2 * f]     = l0 + l2;
                vlo[2 * f + 1] = l1 + l3;
                vhi[2 * f]     = (acc[f][0] + acc[f][2]) - vlo[2 * f];
                vhi[2 * f + 1] = (acc[f][1] + acc[f][3]) - vlo[2 * f + 1];
            }
            float slo = rs8(vlo, lane);
            float shi = rs8(vhi, lane);
            fg[sLo * F_STRIDE + colIdx] += slo;
            fg[sHi * F_STRIDE + colIdx] += shi;
        }

        // stage chunk c+1 into the other buffer (its prior readers finished
        // at the barrier ending iteration c-1)
        if (c + 1 < NCHUNK) {
            float* nx = bufs + ((c + 1) & 1) * BUF_FLOATS;
            #pragma unroll
            for (int j = 0; j < PF_VEC; ++j) {
                float* b0 = nx + (pr0 + j * 16) * RS + pc4;
                b0[0 * QP] = __uint_as_float(f2tf32(pf[j].x));
                b0[1 * QP] = __uint_as_float(f2tf32(pf[j].y));
                b0[2 * QP] = __uint_as_float(f2tf32(pf[j].z));
                b0[3 * QP] = __uint_as_float(f2tf32(pf[j].w));
            }
        }
        __syncthreads();
    }

    // ---- fused classifier: out[s][cc] = (1/30) * sum_e (f0[e]+f1[e]) * W[cc][e] ----
    if (tid < SEG_PB * N_CLS) {
        const int s  = tid / N_CLS;
        const int cc = tid % N_CLS;
        const float* f0 = feats + s * F_STRIDE;
        const float* f1 = feats + (SEG_PB + s) * F_STRIDE;
        const float* wr = W + cc * D_ENC;
        float sum = 0.0f;
        #pragma unroll 8
        for (int e = 0; e < D_ENC; ++e)
            sum += (f0[e] + f1[e]) * __ldg(wr + e);
        out[((long)blk * SEG_PB + s) * N_CLS + cc] = sum * (1.0f / (float)JWIN);
    }
}

extern "C" void kernel_launch(void* const* d_in, const int* in_sizes, int n_in,
                              void* d_out, int out_size) {
    const float* x    = (const float*)d_in[0];   // [1200000, 64]
    const float* Wloc = (const float*)d_in[1];   // [128, 64]
    const float* W    = (const float*)d_in[2];   // [10, 128]
    float* out = (float*)d_out;                  // [40000, 10]

    cudaFuncSetAttribute(classifier_kernel,
                         cudaFuncAttributeMaxDynamicSharedMemorySize, SMEM_BYTES);
    classifier_kernel<<<NBLOCKS, THREADS, SMEM_BYTES>>>(x, Wloc, W, out);
}

// round 12
// speedup vs baseline: 1.2508x; 1.0179x over previous
#include <cuda_runtime.h>
#include <cstdint>

// Problem constants
#define L_TOT      1200000
#define D_IN       64
#define D_ENC      128
#define N_CLS      10
#define JWIN       30
#define ROWS_PB    480                 // 16 segments per block
#define SEG_PB     16
#define NBLOCKS    (L_TOT / ROWS_PB)   // 2500
#define THREADS    256
#define CHUNK_ROWS 64                  // 4 m16-tiles per full chunk
#define NFULL      7                   // 7 full chunks + 1 half chunk (32 rows)

// Permuted smem layout: xs[row][q*QP + t] = tf32(x[row][q + 4*t])
//  -> each lane's A-fragment run (fixed q, t=0..15) is contiguous: LDS.128.
//  QP=20 (16 payload + 4 pad), RS=80 -> LDS.128 phases tile all 32 banks.
#define QP         20
#define RS         80
#define BUF_FLOATS (CHUNK_ROWS * RS)              // 5120
#define F_STRIDE   136
#define FT_FLOATS  (2 * SEG_PB * F_STRIDE)        // 4352 (two m-group planes)
#define SMEM_FLOATS (2 * BUF_FLOATS + FT_FLOATS)  // 14592
#define SMEM_BYTES (SMEM_FLOATS * 4)              // 58368 -> 2 CTAs/SM

__device__ __forceinline__ uint32_t f2tf32(float f) {
    uint32_t u;
    asm("cvt.rna.tf32.f32 %0, %1;" : "=r"(u) : "f"(f));
    return u;
}

__device__ __forceinline__ void mma_tf32(float c[4],
                                         uint32_t a0, uint32_t a1, uint32_t a2, uint32_t a3,
                                         uint32_t b0, uint32_t b1) {
    asm volatile(
        "mma.sync.aligned.m16n8k8.row.col.f32.tf32.tf32.f32 "
        "{%0,%1,%2,%3}, {%4,%5,%6,%7}, {%8,%9}, {%0,%1,%2,%3};"
        : "+f"(c[0]), "+f"(c[1]), "+f"(c[2]), "+f"(c[3])
        : "r"(a0), "r"(a1), "r"(a2), "r"(a3), "r"(b0), "r"(b1));
}

// Reduce-scatter of 8 values across the 8-lane group {lane ^ 4,8,16}.
// Lane ends with the total for value index j = 4*b2 + 2*b3 + b4. 7 shfl + 7 add.
__device__ __forceinline__ float rs8(const float v[8], int lane) {
    float w[4];
    #pragma unroll
    for (int i = 0; i < 4; ++i) {
        float give = (lane & 4) ? v[i] : v[4 + i];
        float keep = (lane & 4) ? v[4 + i] : v[i];
        w[i] = keep + __shfl_xor_sync(0xffffffffu, give, 4);
    }
    float u[2];
    #pragma unroll
    for (int i = 0; i < 2; ++i) {
        float give = (lane & 8) ? w[i] : w[2 + i];
        float keep = (lane & 8) ? w[2 + i] : w[i];
        u[i] = keep + __shfl_xor_sync(0xffffffffu, give, 8);
    }
    float give = (lane & 16) ? u[0] : u[1];
    float keep = (lane & 16) ? u[1] : u[0];
    return keep + __shfl_xor_sync(0xffffffffu, give, 16);
}

// One 16-row m-tile: 8 LDS.128 -> 32 mma -> relu -> pooled accumulate into fg.
__device__ __forceinline__ void do_tile(const float* __restrict__ xs, int ltRow, int rA,
                                        const uint32_t bq[8][4][2],
                                        float* __restrict__ fg,
                                        int lane, int r, int q, int colIdx) {
    float acc[4][4];
    #pragma unroll
    for (int f = 0; f < 4; ++f)
        acc[f][0] = acc[f][1] = acc[f][2] = acc[f][3] = 0.0f;

    const uint4* lo4 = reinterpret_cast<const uint4*>(xs + (ltRow + r) * RS + q * QP);
    const uint4* hi4 = reinterpret_cast<const uint4*>(xs + (ltRow + r + 8) * RS + q * QP);

    #pragma unroll
    for (int j = 0; j < 4; ++j) {
        uint4 lo = lo4[j];              // t=4j..4j+3: ks=2j (x=a0,y=a2), ks=2j+1 (z=a0,w=a2)
        uint4 hi = hi4[j];
        #pragma unroll
        for (int f = 0; f < 4; ++f)
            mma_tf32(acc[f], lo.x, hi.x, lo.y, hi.y, bq[2 * j][f][0], bq[2 * j][f][1]);
        #pragma unroll
        for (int f = 0; f < 4; ++f)
            mma_tf32(acc[f], lo.z, hi.z, lo.w, hi.w, bq[2 * j + 1][f][0], bq[2 * j + 1][f][1]);
    }

    // relu
    #pragma unroll
    for (int f = 0; f < 4; ++f) {
        acc[f][0] = fmaxf(acc[f][0], 0.0f);
        acc[f][1] = fmaxf(acc[f][1], 0.0f);
        acc[f][2] = fmaxf(acc[f][2], 0.0f);
        acc[f][3] = fmaxf(acc[f][3], 0.0f);
    }

    const int sLo = rA / JWIN;
    const int sHi = (rA + 15) / JWIN;

    if (sLo == sHi) {
        float v[8];
        #pragma unroll
        for (int f = 0; f < 4; ++f) {
            v[2 * f]     = acc[f][0] + acc[f][2];
            v[2 * f + 1] = acc[f][1] + acc[f][3];
        }
        fg[sLo * F_STRIDE + colIdx] += rs8(v, lane);
    } else {
        const int b = sHi * JWIN - rA;
        const bool pL = (r < b);
        const bool pH = (r + 8 < b);
        float vlo[8], vhi[8];
        #pragma unroll
        for (int f = 0; f < 4; ++f) {
            float l0 = pL ? acc[f][0] : 0.0f;
            float l1 = pL ? acc[f][1] : 0.0f;
            float l2 = pH ? acc[f][2] : 0.0f;
            float l3 = pH ? acc[f][3] : 0.0f;
            vlo[2 * f]     = l0 + l2;
            vlo[2 * f + 1] = l1 + l3;
            vhi[2 * f]     = (acc[f][0] + acc[f][2]) - vlo[2 * f];
            vhi[2 * f + 1] = (acc[f][1] + acc[f][3]) - vlo[2 * f + 1];
        }
        float slo = rs8(vlo, lane);
        float shi = rs8(vhi, lane);
        fg[sLo * F_STRIDE + colIdx] += slo;
        fg[sHi * F_STRIDE + colIdx] += shi;
    }
}

__global__ __launch_bounds__(THREADS, 2)
void classifier_kernel(const float* __restrict__ x,
                       const float* __restrict__ Wloc,
                       const float* __restrict__ W,
                       float* __restrict__ out) {
    extern __shared__ float smem[];
    float* bufs  = smem;                          // 2 x [64][80] tf32-bits
    float* feats = smem + 2 * BUF_FLOATS;         // [2][16][136] fp32 partials

    const int tid = threadIdx.x;
    const int blk = blockIdx.x;
    const long rowBase = (long)blk * ROWS_PB;

    const int lane  = tid & 31;
    const int wid   = tid >> 5;
    const int g     = wid & 1;           // m-group
    const int strip = wid >> 1;          // 4 n-strips of 32 cols
    const int nb    = strip * 32;
    const int r     = lane >> 2;
    const int q     = lane & 3;

    const int colIdx = nb
        + (2 * ((lane >> 2) & 1) + ((lane >> 3) & 1)) * 8
        + 2 * q
        + ((lane >> 4) & 1);

    // staging wave geometry: wave w covers 32 rows [32w, 32w+32) of a chunk;
    // element i = j*256 + tid -> local row (i>>4), float4-col (i&15)
    const int wr0 = tid >> 4;            // row within wave for j=0 (j adds 16)
    const int wc4 = tid & 15;

    // ---- prologue: LDG wave0 of chunk 0 (start DRAM immediately) ----
    float4 pf[2];
    {
        const float4* s4 = reinterpret_cast<const float4*>(x + rowBase * D_IN);
        pf[0] = s4[tid];
        pf[1] = s4[THREADS + tid];
    }

    // zero feats (overlaps LDG)
    for (int i = tid; i < FT_FLOATS; i += THREADS) feats[i] = 0.0f;

    // B frag (m16n8k8, col): n = nb + f*8 + r, k = ks*8 + q (+4 for b1)
    uint32_t bq[8][4][2];
    {
        const float* wb = Wloc + (nb + r) * D_IN + q;
        #pragma unroll
        for (int ks = 0; ks < 8; ++ks) {
            #pragma unroll
            for (int f = 0; f < 4; ++f) {
                bq[ks][f][0] = f2tf32(__ldg(wb + f * 8 * D_IN + ks * 8));
                bq[ks][f][1] = f2tf32(__ldg(wb + f * 8 * D_IN + ks * 8 + 4));
            }
        }
    }

    // stage wave0 of chunk 0, then LDG+stage wave1 of chunk 0
    #pragma unroll
    for (int j = 0; j < 2; ++j) {
        float* b0 = bufs + (wr0 + j * 16) * RS + wc4;
        b0[0 * QP] = __uint_as_float(f2tf32(pf[j].x));
        b0[1 * QP] = __uint_as_float(f2tf32(pf[j].y));
        b0[2 * QP] = __uint_as_float(f2tf32(pf[j].z));
        b0[3 * QP] = __uint_as_float(f2tf32(pf[j].w));
    }
    {
        const float4* s4 = reinterpret_cast<const float4*>(x + (rowBase + 32) * D_IN);
        pf[0] = s4[tid];
        pf[1] = s4[THREADS + tid];
    }
    #pragma unroll
    for (int j = 0; j < 2; ++j) {
        float* b0 = bufs + (32 + wr0 + j * 16) * RS + wc4;
        b0[0 * QP] = __uint_as_float(f2tf32(pf[j].x));
        b0[1 * QP] = __uint_as_float(f2tf32(pf[j].y));
        b0[2 * QP] = __uint_as_float(f2tf32(pf[j].z));
        b0[3 * QP] = __uint_as_float(f2tf32(pf[j].w));
    }
    __syncthreads();

    float* fg = feats + g * SEG_PB * F_STRIDE;

    // ---- mainloop: 7 full chunks, 2 tile-passes per warp per barrier ----
    #pragma unroll
    for (int c = 0; c < NFULL; ++c) {
        const float* xs = bufs + (c & 1) * BUF_FLOATS;
        float* nx = bufs + ((c + 1) & 1) * BUF_FLOATS;

        // LDG wave0 of chunk c+1 (always valid: chunk 7 is the 32-row half chunk)
        {
            const float4* s4 = reinterpret_cast<const float4*>(
                x + (rowBase + (long)(c + 1) * CHUNK_ROWS) * D_IN);
            pf[0] = s4[tid];
            pf[1] = s4[THREADS + tid];
        }

        // pass A: tile g (rows 64c + 16g)
        do_tile(xs, 16 * g, c * CHUNK_ROWS + 16 * g, bq, fg, lane, r, q, colIdx);

        // STS wave0 of chunk c+1 (target buffer free since barrier of chunk c-1)
        #pragma unroll
        for (int j = 0; j < 2; ++j) {
            float* b0 = nx + (wr0 + j * 16) * RS + wc4;
            b0[0 * QP] = __uint_as_float(f2tf32(pf[j].x));
            b0[1 * QP] = __uint_as_float(f2tf32(pf[j].y));
            b0[2 * QP] = __uint_as_float(f2tf32(pf[j].z));
            b0[3 * QP] = __uint_as_float(f2tf32(pf[j].w));
        }

        // LDG wave1 of chunk c+1 (skip for c==6: half chunk has only 32 rows)
        if (c + 1 < NFULL) {
            const float4* s4 = reinterpret_cast<const float4*>(
                x + (rowBase + (long)(c + 1) * CHUNK_ROWS + 32) * D_IN);
            pf[0] = s4[tid];
            pf[1] = s4[THREADS + tid];
        }

        // pass B: tile g+2 (rows 64c + 32 + 16g)
        do_tile(xs, 32 + 16 * g, c * CHUNK_ROWS + 32 + 16 * g, bq, fg, lane, r, q, colIdx);

        // STS wave1 of chunk c+1
        if (c + 1 < NFULL) {
            #pragma unroll
            for (int j = 0; j < 2; ++j) {
                float* b0 = nx + (32 + wr0 + j * 16) * RS + wc4;
                b0[0 * QP] = __uint_as_float(f2tf32(pf[j].x));
                b0[1 * QP] = __uint_as_float(f2tf32(pf[j].y));
                b0[2 * QP] = __uint_as_float(f2tf32(pf[j].z));
                b0[3 * QP] = __uint_as_float(f2tf32(pf[j].w));
            }
        }
        __syncthreads();
    }

    // ---- half chunk (rows 448..479): one tile per m-group, buffer 1 ----
    {
        const float* xs = bufs + (NFULL & 1) * BUF_FLOATS;
        do_tile(xs, 16 * g, NFULL * CHUNK_ROWS + 16 * g, bq, fg, lane, r, q, colIdx);
    }
    __syncthreads();

    // ---- fused classifier (vectorized): out[s][cc] = (1/30)*sum_e (f0+f1)*W ----
    if (tid < SEG_PB * N_CLS) {
        const int s  = tid / N_CLS;
        const int cc = tid - s * N_CLS;
        const float4* f0 = reinterpret_cast<const float4*>(feats + s * F_STRIDE);
        const float4* f1 = reinterpret_cast<const float4*>(feats + (SEG_PB + s) * F_STRIDE);
        const float4* wr = reinterpret_cast<const float4*>(W + cc * D_ENC);
        float sum = 0.0f;
        #pragma unroll
        for (int e4 = 0; e4 < D_ENC / 4; ++e4) {
            float4 a = f0[e4];
            float4 b = f1[e4];
            float4 w4 = __ldg(&wr[e4]);
            sum += (a.x + b.x) * w4.x + (a.y + b.y) * w4.y
                 + (a.z + b.z) * w4.z + (a.w + b.w) * w4.w;
        }
        out[((long)blk * SEG_PB + s) * N_CLS + cc] = sum * (1.0f / (float)JWIN);
    }
}

extern "C" void kernel_launch(void* const* d_in, const int* in_sizes, int n_in,
                              void* d_out, int out_size) {
    const float* x    = (const float*)d_in[0];   // [1200000, 64]
    const float* Wloc = (const float*)d_in[1];   // [128, 64]
    const float* W    = (const float*)d_in[2];   // [10, 128]
    float* out = (float*)d_out;                  // [40000, 10]

    cudaFuncSetAttribute(classifier_kernel,
                         cudaFuncAttributeMaxDynamicSharedMemorySize, SMEM_BYTES);
    classifier_kernel<<<NBLOCKS, THREADS, SMEM_BYTES>>>(x, Wloc, W, out);
}

// round 14
// speedup vs baseline: 1.4941x; 1.1945x over previous
#include <cuda_runtime.h>
#include <cuda_fp16.h>
#include <cstdint>

// Problem constants
#define L_TOT      1200000
#define D_IN       64
#define D_ENC      128
#define N_CLS      10
#define JWIN       30
#define ROWS_PB    480                 // 16 segments per block
#define SEG_PB     16
#define NBLOCKS    (L_TOT / ROWS_PB)   // 2500
#define THREADS    256
#define CHUNK_ROWS 64                  // 4 m16-tiles per full chunk
#define NFULL      7                   // 7 full chunks + 1 half chunk (32 rows)

// fp16 staged rows: 64 halfs payload, permuted by pair so lane q's 8 pairs
// (pair p == q mod 4) are contiguous: pair p -> 4B-word (p&3)*8 + (p>>2).
// Row padded to 144B (36 words): LDS.128 phases conflict-free (9r+2q mod 8 distinct).
#define RSB        144
#define BUF_BYTES  (CHUNK_ROWS * RSB)             // 9216
#define F_STRIDE   136
#define FT_FLOATS  (2 * SEG_PB * F_STRIDE)        // 4352 (two m-group planes)
#define SMEM_BYTES (2 * BUF_BYTES + FT_FLOATS * 4)  // 35840 B

__device__ __forceinline__ uint32_t pack_h2(float lo, float hi) {
    uint32_t r;
    asm("cvt.rn.f16x2.f32 %0, %1, %2;" : "=r"(r) : "f"(hi), "f"(lo));
    return r;
}

__device__ __forceinline__ void mma_f16(float c[4],
                                        uint32_t a0, uint32_t a1, uint32_t a2, uint32_t a3,
                                        uint32_t b0, uint32_t b1) {
    asm volatile(
        "mma.sync.aligned.m16n8k16.row.col.f32.f16.f16.f32 "
        "{%0,%1,%2,%3}, {%4,%5,%6,%7}, {%8,%9}, {%0,%1,%2,%3};"
        : "+f"(c[0]), "+f"(c[1]), "+f"(c[2]), "+f"(c[3])
        : "r"(a0), "r"(a1), "r"(a2), "r"(a3), "r"(b0), "r"(b1));
}

// Reduce-scatter of 8 values across the 8-lane group {lane ^ 4,8,16}.
// Lane ends with the total for value index j = 4*b2 + 2*b3 + b4. 7 shfl + 7 add.
__device__ __forceinline__ float rs8(const float v[8], int lane) {
    float w[4];
    #pragma unroll
    for (int i = 0; i < 4; ++i) {
        float give = (lane & 4) ? v[i] : v[4 + i];
        float keep = (lane & 4) ? v[4 + i] : v[i];
        w[i] = keep + __shfl_xor_sync(0xffffffffu, give, 4);
    }
    float u[2];
    #pragma unroll
    for (int i = 0; i < 2; ++i) {
        float give = (lane & 8) ? w[i] : w[2 + i];
        float keep = (lane & 8) ? w[2 + i] : w[i];
        u[i] = keep + __shfl_xor_sync(0xffffffffu, give, 8);
    }
    float give = (lane & 16) ? u[0] : u[1];
    float keep = (lane & 16) ? u[1] : u[0];
    return keep + __shfl_xor_sync(0xffffffffu, give, 16);
}

// One 16-row m-tile: 4 LDS.128 -> 16 mma(k16) -> relu -> pooled accumulate.
__device__ __forceinline__ void do_tile(const char* __restrict__ xb, int ltRow, int rA,
                                        const uint32_t bq[4][4][2],
                                        float* __restrict__ fg,
                                        int lane, int r, int q, int colIdx) {
    float acc[4][4];
    #pragma unroll
    for (int f = 0; f < 4; ++f)
        acc[f][0] = acc[f][1] = acc[f][2] = acc[f][3] = 0.0f;

    const uint4* lo4 = reinterpret_cast<const uint4*>(xb + (ltRow + r) * RSB + q * 32);
    const uint4* hi4 = reinterpret_cast<const uint4*>(xb + (ltRow + r + 8) * RSB + q * 32);
    uint4 L0 = lo4[0], L1 = lo4[1];
    uint4 H0 = hi4[0], H1 = hi4[1];

    // ks0: a={L0.x,H0.x,L0.y,H0.y}  ks1: {L0.z,H0.z,L0.w,H0.w}
    // ks2: a={L1.x,H1.x,L1.y,H1.y}  ks3: {L1.z,H1.z,L1.w,H1.w}
    #pragma unroll
    for (int f = 0; f < 4; ++f)
        mma_f16(acc[f], L0.x, H0.x, L0.y, H0.y, bq[0][f][0], bq[0][f][1]);
    #pragma unroll
    for (int f = 0; f < 4; ++f)
        mma_f16(acc[f], L0.z, H0.z, L0.w, H0.w, bq[1][f][0], bq[1][f][1]);
    #pragma unroll
    for (int f = 0; f < 4; ++f)
        mma_f16(acc[f], L1.x, H1.x, L1.y, H1.y, bq[2][f][0], bq[2][f][1]);
    #pragma unroll
    for (int f = 0; f < 4; ++f)
        mma_f16(acc[f], L1.z, H1.z, L1.w, H1.w, bq[3][f][0], bq[3][f][1]);

    // relu
    #pragma unroll
    for (int f = 0; f < 4; ++f) {
        acc[f][0] = fmaxf(acc[f][0], 0.0f);
        acc[f][1] = fmaxf(acc[f][1], 0.0f);
        acc[f][2] = fmaxf(acc[f][2], 0.0f);
        acc[f][3] = fmaxf(acc[f][3], 0.0f);
    }

    const int sLo = rA / JWIN;
    const int sHi = (rA + 15) / JWIN;

    if (sLo == sHi) {
        float v[8];
        #pragma unroll
        for (int f = 0; f < 4; ++f) {
            v[2 * f]     = acc[f][0] + acc[f][2];
            v[2 * f + 1] = acc[f][1] + acc[f][3];
        }
        fg[sLo * F_STRIDE + colIdx] += rs8(v, lane);
    } else {
        const int b = sHi * JWIN - rA;
        const bool pL = (r < b);
        const bool pH = (r + 8 < b);
        float vlo[8], vhi[8];
        #pragma unroll
        for (int f = 0; f < 4; ++f) {
            float l0 = pL ? acc[f][0] : 0.0f;
            float l1 = pL ? acc[f][1] : 0.0f;
            float l2 = pH ? acc[f][2] : 0.0f;
            float l3 = pH ? acc[f][3] : 0.0f;
            vlo[2 * f]     = l0 + l2;
            vlo[2 * f + 1] = l1 + l3;
            vhi[2 * f]     = (acc[f][0] + acc[f][2]) - vlo[2 * f];
            vhi[2 * f + 1] = (acc[f][1] + acc[f][3]) - vlo[2 * f + 1];
        }
        float slo = rs8(vlo, lane);
        float shi = rs8(vhi, lane);
        fg[sLo * F_STRIDE + colIdx] += slo;
        fg[sHi * F_STRIDE + colIdx] += shi;
    }
}

__global__ __launch_bounds__(THREADS, 2)
void classifier_kernel(const float* __restrict__ x,
                       const float* __restrict__ Wloc,
                       const float* __restrict__ W,
                       float* __restrict__ out) {
    extern __shared__ char smem[];
    char* bufs   = smem;                          // 2 x [64 rows][144B] fp16 perm
    float* feats = reinterpret_cast<float*>(smem + 2 * BUF_BYTES);  // [2][16][136]

    const int tid = threadIdx.x;
    const int blk = blockIdx.x;
    const long rowBase = (long)blk * ROWS_PB;

    const int lane  = tid & 31;
    const int wid   = tid >> 5;
    const int g     = wid & 1;           // m-group
    const int strip = wid >> 1;          // 4 n-strips of 32 cols
    const int nb    = strip * 32;
    const int r     = lane >> 2;
    const int q     = lane & 3;

    const int colIdx = nb
        + (2 * ((lane >> 2) & 1) + ((lane >> 3) & 1)) * 8
        + 2 * q
        + ((lane >> 4) & 1);

    // staging geometry: wave = 32 rows; thread handles rows wr0, wr0+16, float4-col wc4
    const int wr0 = tid >> 4;
    const int wc4 = tid & 15;
    // word slots within a row for this thread's two pairs (p=2wc4, 2wc4+1)
    const int w0 = 16 * (wc4 & 1) + (wc4 >> 1);   // second pair at w0+8

    // ---- prologue: LDG wave0 of chunk 0 (start DRAM immediately) ----
    float4 pf[2];
    {
        const float4* s4 = reinterpret_cast<const float4*>(x + rowBase * D_IN);
        pf[0] = s4[tid];
        pf[1] = s4[THREADS + tid];
    }

    // zero feats (overlaps LDG)
    for (int i = tid; i < FT_FLOATS; i += THREADS) feats[i] = 0.0f;

    // B frags fp16 (m16n8k16, col): n = nb + 8f + r; b0 k=16ks+2q(+1), b1 +8
    uint32_t bq[4][4][2];
    {
        const float* wb = Wloc + (nb + r) * D_IN + 2 * q;
        #pragma unroll
        for (int ks = 0; ks < 4; ++ks) {
            #pragma unroll
            for (int f = 0; f < 4; ++f) {
                float2 v0 = __ldg(reinterpret_cast<const float2*>(wb + f * 8 * D_IN + ks * 16));
                float2 v1 = __ldg(reinterpret_cast<const float2*>(wb + f * 8 * D_IN + ks * 16 + 8));
                bq[ks][f][0] = pack_h2(v0.x, v0.y);
                bq[ks][f][1] = pack_h2(v1.x, v1.y);
            }
        }
    }

    // stage wave0 of chunk 0, then LDG+stage wave1 of chunk 0
    #pragma unroll
    for (int j = 0; j < 2; ++j) {
        uint32_t* rowp = reinterpret_cast<uint32_t*>(bufs + (wr0 + j * 16) * RSB);
        rowp[w0]     = pack_h2(pf[j].x, pf[j].y);
        rowp[w0 + 8] = pack_h2(pf[j].z, pf[j].w);
    }
    {
        const float4* s4 = reinterpret_cast<const float4*>(x + (rowBase + 32) * D_IN);
        pf[0] = s4[tid];
        pf[1] = s4[THREADS + tid];
    }
    #pragma unroll
    for (int j = 0; j < 2; ++j) {
        uint32_t* rowp = reinterpret_cast<uint32_t*>(bufs + (32 + wr0 + j * 16) * RSB);
        rowp[w0]     = pack_h2(pf[j].x, pf[j].y);
        rowp[w0 + 8] = pack_h2(pf[j].z, pf[j].w);
    }
    __syncthreads();

    float* fg = feats + g * SEG_PB * F_STRIDE;

    // ---- mainloop: 7 full chunks, 2 tile-passes per warp per barrier ----
    #pragma unroll
    for (int c = 0; c < NFULL; ++c) {
        const char* xb = bufs + (c & 1) * BUF_BYTES;
        char* nx = bufs + ((c + 1) & 1) * BUF_BYTES;

        // LDG wave0 of chunk c+1 (chunk 7 = 32-row half chunk, wave0 only)
        {
            const float4* s4 = reinterpret_cast<const float4*>(
                x + (rowBase + (long)(c + 1) * CHUNK_ROWS) * D_IN);
            pf[0] = s4[tid];
            pf[1] = s4[THREADS + tid];
        }

        // pass A: tile g
        do_tile(xb, 16 * g, c * CHUNK_ROWS + 16 * g, bq, fg, lane, r, q, colIdx);

        // STS wave0 of chunk c+1
        #pragma unroll
        for (int j = 0; j < 2; ++j) {
            uint32_t* rowp = reinterpret_cast<uint32_t*>(nx + (wr0 + j * 16) * RSB);
            rowp[w0]     = pack_h2(pf[j].x, pf[j].y);
            rowp[w0 + 8] = pack_h2(pf[j].z, pf[j].w);
        }

        // LDG wave1 of chunk c+1 (skip for c==6)
        if (c + 1 < NFULL) {
            const float4* s4 = reinterpret_cast<const float4*>(
                x + (rowBase + (long)(c + 1) * CHUNK_ROWS + 32) * D_IN);
            pf[0] = s4[tid];
            pf[1] = s4[THREADS + tid];
        }

        // pass B: tile g+2
        do_tile(xb, 32 + 16 * g, c * CHUNK_ROWS + 32 + 16 * g, bq, fg, lane, r, q, colIdx);

        // STS wave1 of chunk c+1
        if (c + 1 < NFULL) {
            #pragma unroll
            for (int j = 0; j < 2; ++j) {
                uint32_t* rowp = reinterpret_cast<uint32_t*>(nx + (32 + wr0 + j * 16) * RSB);
                rowp[w0]     = pack_h2(pf[j].x, pf[j].y);
                rowp[w0 + 8] = pack_h2(pf[j].z, pf[j].w);
            }
        }
        __syncthreads();
    }

    // ---- half chunk (rows 448..479): one tile per m-group, buffer 1 ----
    {
        const char* xb = bufs + (NFULL & 1) * BUF_BYTES;
        do_tile(xb, 16 * g, NFULL * CHUNK_ROWS + 16 * g, bq, fg, lane, r, q, colIdx);
    }
    __syncthreads();

    // ---- fused classifier (vectorized): out[s][cc] = (1/30)*sum_e (f0+f1)*W ----
    if (tid < SEG_PB * N_CLS) {
        const int s  = tid / N_CLS;
        const int cc = tid - s * N_CLS;
        const float4* f0 = reinterpret_cast<const float4*>(feats + s * F_STRIDE);
        const float4* f1 = reinterpret_cast<const float4*>(feats + (SEG_PB + s) * F_STRIDE);
        const float4* wr = reinterpret_cast<const float4*>(W + cc * D_ENC);
        float sum = 0.0f;
        #pragma unroll
        for (int e4 = 0; e4 < D_ENC / 4; ++e4) {
            float4 a = f0[e4];
            float4 b = f1[e4];
            float4 w4 = __ldg(&wr[e4]);
            sum += (a.x + b.x) * w4.x + (a.y + b.y) * w4.y
                 + (a.z + b.z) * w4.z + (a.w + b.w) * w4.w;
        }
        out[((long)blk * SEG_PB + s) * N_CLS + cc] = sum * (1.0f / (float)JWIN);
    }
}

extern "C" void kernel_launch(void* const* d_in, const int* in_sizes, int n_in,
                              void* d_out, int out_size) {
    const float* x    = (const float*)d_in[0];   // [1200000, 64]
    const float* Wloc = (const float*)d_in[1];   // [128, 64]
    const float* W    = (const float*)d_in[2];   // [10, 128]
    float* out = (float*)d_out;                  // [40000, 10]

    cudaFuncSetAttribute(classifier_kernel,
                         cudaFuncAttributeMaxDynamicSharedMemorySize, SMEM_BYTES);
    classifier_kernel<<<NBLOCKS, THREADS, SMEM_BYTES>>>(x, Wloc, W, out);
}

// round 15
// speedup vs baseline: 1.7781x; 1.1901x over previous
#include <cuda_runtime.h>
#include <cuda_fp16.h>
#include <cstdint>

// Problem constants
#define L_TOT      1200000
#define D_IN       64
#define D_ENC      128
#define N_CLS      10
#define JWIN       30
#define ROWS_PB    480                 // 16 segments per block
#define SEG_PB     16
#define NBLOCKS    (L_TOT / ROWS_PB)   // 2500
#define THREADS    128                 // 4 warps = 4 n-strips; 4 CTAs/SM
#define CHUNK_ROWS 32                  // 2 m16-tiles per chunk
#define NCHUNK     (ROWS_PB / CHUNK_ROWS)   // 15

// fp16 staged rows: 64 halfs payload, permuted by pair so lane q's 8 pairs
// (pair p == q mod 4) are contiguous: pair p -> 4B-word (p&3)*8 + (p>>2).
// Row padded to 144B (36 words): LDS.128 phases conflict-free.
#define RSB        144
#define BUF_BYTES  (CHUNK_ROWS * RSB)             // 4608
#define F_STRIDE   136
#define FT_FLOATS  (SEG_PB * F_STRIDE)            // 2176 (single plane)
#define SMEM_BYTES (2 * BUF_BYTES + FT_FLOATS * 4)  // 17920 B -> 4 CTAs/SM

__device__ __forceinline__ uint32_t pack_h2(float lo, float hi) {
    uint32_t r;
    asm("cvt.rn.f16x2.f32 %0, %1, %2;" : "=r"(r) : "f"(hi), "f"(lo));
    return r;
}

__device__ __forceinline__ void mma_f16(float c[4],
                                        uint32_t a0, uint32_t a1, uint32_t a2, uint32_t a3,
                                        uint32_t b0, uint32_t b1) {
    asm volatile(
        "mma.sync.aligned.m16n8k16.row.col.f32.f16.f16.f32 "
        "{%0,%1,%2,%3}, {%4,%5,%6,%7}, {%8,%9}, {%0,%1,%2,%3};"
        : "+f"(c[0]), "+f"(c[1]), "+f"(c[2]), "+f"(c[3])
        : "r"(a0), "r"(a1), "r"(a2), "r"(a3), "r"(b0), "r"(b1));
}

// Reduce-scatter of 8 values across the 8-lane group {lane ^ 4,8,16}.
// Lane ends with the total for value index j = 4*b2 + 2*b3 + b4. 7 shfl + 7 add.
__device__ __forceinline__ float rs8(const float v[8], int lane) {
    float w[4];
    #pragma unroll
    for (int i = 0; i < 4; ++i) {
        float give = (lane & 4) ? v[i] : v[4 + i];
        float keep = (lane & 4) ? v[4 + i] : v[i];
        w[i] = keep + __shfl_xor_sync(0xffffffffu, give, 4);
    }
    float u[2];
    #pragma unroll
    for (int i = 0; i < 2; ++i) {
        float give = (lane & 8) ? w[i] : w[2 + i];
        float keep = (lane & 8) ? w[2 + i] : w[i];
        u[i] = keep + __shfl_xor_sync(0xffffffffu, give, 8);
    }
    float give = (lane & 16) ? u[0] : u[1];
    float keep = (lane & 16) ? u[1] : u[0];
    return keep + __shfl_xor_sync(0xffffffffu, give, 16);
}

// One 16-row m-tile: 4 LDS.128 -> 16 mma(k16) -> relu -> pooled accumulate.
__device__ __forceinline__ void do_tile(const char* __restrict__ xb, int ltRow, int rA,
                                        const uint32_t bq[4][4][2],
                                        float* __restrict__ fg,
                                        int lane, int r, int q, int colIdx) {
    float acc[4][4];
    #pragma unroll
    for (int f = 0; f < 4; ++f)
        acc[f][0] = acc[f][1] = acc[f][2] = acc[f][3] = 0.0f;

    const uint4* lo4 = reinterpret_cast<const uint4*>(xb + (ltRow + r) * RSB + q * 32);
    const uint4* hi4 = reinterpret_cast<const uint4*>(xb + (ltRow + r + 8) * RSB + q * 32);
    uint4 L0 = lo4[0], L1 = lo4[1];
    uint4 H0 = hi4[0], H1 = hi4[1];

    #pragma unroll
    for (int f = 0; f < 4; ++f)
        mma_f16(acc[f], L0.x, H0.x, L0.y, H0.y, bq[0][f][0], bq[0][f][1]);
    #pragma unroll
    for (int f = 0; f < 4; ++f)
        mma_f16(acc[f], L0.z, H0.z, L0.w, H0.w, bq[1][f][0], bq[1][f][1]);
    #pragma unroll
    for (int f = 0; f < 4; ++f)
        mma_f16(acc[f], L1.x, H1.x, L1.y, H1.y, bq[2][f][0], bq[2][f][1]);
    #pragma unroll
    for (int f = 0; f < 4; ++f)
        mma_f16(acc[f], L1.z, H1.z, L1.w, H1.w, bq[3][f][0], bq[3][f][1]);

    // relu
    #pragma unroll
    for (int f = 0; f < 4; ++f) {
        acc[f][0] = fmaxf(acc[f][0], 0.0f);
        acc[f][1] = fmaxf(acc[f][1], 0.0f);
        acc[f][2] = fmaxf(acc[f][2], 0.0f);
        acc[f][3] = fmaxf(acc[f][3], 0.0f);
    }

    const int sLo = rA / JWIN;
    const int sHi = (rA + 15) / JWIN;

    if (sLo == sHi) {
        float v[8];
        #pragma unroll
        for (int f = 0; f < 4; ++f) {
            v[2 * f]     = acc[f][0] + acc[f][2];
            v[2 * f + 1] = acc[f][1] + acc[f][3];
        }
        fg[sLo * F_STRIDE + colIdx] += rs8(v, lane);
    } else {
        const int b = sHi * JWIN - rA;
        const bool pL = (r < b);
        const bool pH = (r + 8 < b);
        float vlo[8], vhi[8];
        #pragma unroll
        for (int f = 0; f < 4; ++f) {
            float l0 = pL ? acc[f][0] : 0.0f;
            float l1 = pL ? acc[f][1] : 0.0f;
            float l2 = pH ? acc[f][2] : 0.0f;
            float l3 = pH ? acc[f][3] : 0.0f;
            vlo[2 * f]     = l0 + l2;
            vlo[2 * f + 1] = l1 + l3;
            vhi[2 * f]     = (acc[f][0] + acc[f][2]) - vlo[2 * f];
            vhi[2 * f + 1] = (acc[f][1] + acc[f][3]) - vlo[2 * f + 1];
        }
        float slo = rs8(vlo, lane);
        float shi = rs8(vhi, lane);
        fg[sLo * F_STRIDE + colIdx] += slo;
        fg[sHi * F_STRIDE + colIdx] += shi;
    }
}

__global__ __launch_bounds__(THREADS, 4)
void classifier_kernel(const float* __restrict__ x,
                       const float* __restrict__ Wloc,
                       const float* __restrict__ W,
                       float* __restrict__ out) {
    extern __shared__ char smem[];
    char* bufs   = smem;                          // 2 x [32 rows][144B] fp16 perm
    float* feats = reinterpret_cast<float*>(smem + 2 * BUF_BYTES);  // [16][136]

    const int tid = threadIdx.x;
    const int blk = blockIdx.x;
    const long rowBase = (long)blk * ROWS_PB;

    const int lane = tid & 31;
    const int wid  = tid >> 5;
    const int nb   = wid * 32;           // this warp's 32-col n-strip
    const int r    = lane >> 2;
    const int q    = lane & 3;

    const int colIdx = nb
        + (2 * ((lane >> 2) & 1) + ((lane >> 3) & 1)) * 8
        + 2 * q
        + ((lane >> 4) & 1);

    // staging geometry: element i = j*128 + tid -> row j*8 + (tid>>4), f4-col tid&15
    const int pr0 = tid >> 4;            // base row (0..7); j adds 8
    const int wc4 = tid & 15;
    const int w0 = 16 * (wc4 & 1) + (wc4 >> 1);   // word slot; 2nd pair at w0+8

    // ---- prologue: LDG chunk 0 (start DRAM immediately) ----
    float4 pf[4];
    {
        const float4* s4 = reinterpret_cast<const float4*>(x + rowBase * D_IN);
        #pragma unroll
        for (int j = 0; j < 4; ++j) pf[j] = s4[j * THREADS + tid];
    }

    // zero feats (overlaps LDG)
    for (int i = tid; i < FT_FLOATS; i += THREADS) feats[i] = 0.0f;

    // B frags fp16 (m16n8k16, col): n = nb + 8f + r; b0 k=16ks+2q(+1), b1 +8
    uint32_t bq[4][4][2];
    {
        const float* wb = Wloc + (nb + r) * D_IN + 2 * q;
        #pragma unroll
        for (int ks = 0; ks < 4; ++ks) {
            #pragma unroll
            for (int f = 0; f < 4; ++f) {
                float2 v0 = __ldg(reinterpret_cast<const float2*>(wb + f * 8 * D_IN + ks * 16));
                float2 v1 = __ldg(reinterpret_cast<const float2*>(wb + f * 8 * D_IN + ks * 16 + 8));
                bq[ks][f][0] = pack_h2(v0.x, v0.y);
                bq[ks][f][1] = pack_h2(v1.x, v1.y);
            }
        }
    }

    // stage chunk 0 into buffer 0
    #pragma unroll
    for (int j = 0; j < 4; ++j) {
        uint32_t* rowp = reinterpret_cast<uint32_t*>(bufs + (pr0 + j * 8) * RSB);
        rowp[w0]     = pack_h2(pf[j].x, pf[j].y);
        rowp[w0 + 8] = pack_h2(pf[j].z, pf[j].w);
    }
    __syncthreads();

    // ---- mainloop: 15 chunks, 2 tiles per warp per barrier ----
    #pragma unroll
    for (int c = 0; c < NCHUNK; ++c) {
        const char* xb = bufs + (c & 1) * BUF_BYTES;
        char* nx = bufs + ((c + 1) & 1) * BUF_BYTES;

        // LDG chunk c+1
        if (c + 1 < NCHUNK) {
            const float4* s4 = reinterpret_cast<const float4*>(
                x + (rowBase + (long)(c + 1) * CHUNK_ROWS) * D_IN);
            #pragma unroll
            for (int j = 0; j < 4; ++j) pf[j] = s4[j * THREADS + tid];
        }

        // tile 0 (rows 32c .. 32c+15) — covers LDG latency
        do_tile(xb, 0, c * CHUNK_ROWS, bq, feats, lane, r, q, colIdx);

        // STS chunk c+1 (target buffer free since barrier ending chunk c-1)
        if (c + 1 < NCHUNK) {
            #pragma unroll
            for (int j = 0; j < 4; ++j) {
                uint32_t* rowp = reinterpret_cast<uint32_t*>(nx + (pr0 + j * 8) * RSB);
                rowp[w0]     = pack_h2(pf[j].x, pf[j].y);
                rowp[w0 + 8] = pack_h2(pf[j].z, pf[j].w);
            }
        }

        // tile 1 (rows 32c+16 .. 32c+31) — same warp, same feats cols: no race
        do_tile(xb, 16, c * CHUNK_ROWS + 16, bq, feats, lane, r, q, colIdx);

        __syncthreads();
    }

    // ---- fused classifier: out[s][cc] = (1/30) * sum_e feats[s][e] * W[cc][e] ----
    for (int t = tid; t < SEG_PB * N_CLS; t += THREADS) {
        const int s  = t / N_CLS;
        const int cc = t - s * N_CLS;
        const float4* fr = reinterpret_cast<const float4*>(feats + s * F_STRIDE);
        const float4* wr = reinterpret_cast<const float4*>(W + cc * D_ENC);
        float sum = 0.0f;
        #pragma unroll
        for (int e4 = 0; e4 < D_ENC / 4; ++e4) {
            float4 a = fr[e4];
            float4 w4 = __ldg(&wr[e4]);
            sum += a.x * w4.x + a.y * w4.y + a.z * w4.z + a.w * w4.w;
        }
        out[((long)blk * SEG_PB + s) * N_CLS + cc] = sum * (1.0f / (float)JWIN);
    }
}

extern "C" void kernel_launch(void* const* d_in, const int* in_sizes, int n_in,
                              void* d_out, int out_size) {
    const float* x    = (const float*)d_in[0];   // [1200000, 64]
    const float* Wloc = (const float*)d_in[1];   // [128, 64]
    const float* W    = (const float*)d_in[2];   // [10, 128]
    float* out = (float*)d_out;                  // [40000, 10]

    cudaFuncSetAttribute(classifier_kernel,
                         cudaFuncAttributeMaxDynamicSharedMemorySize, SMEM_BYTES);
    classifier_kernel<<<NBLOCKS, THREADS, SMEM_BYTES>>>(x, Wloc, W, out);
}

// round 17
// speedup vs baseline: 1.9036x; 1.0706x over previous
#include <cuda_runtime.h>
#include <cuda_fp16.h>
#include <cstdint>

// Problem constants
#define L_TOT      1200000
#define D_IN       64
#define D_ENC      128
#define N_CLS      10
#define JWIN       30
#define ROWS_PB    480                 // 16 segments per block
#define SEG_PB     16
#define NBLOCKS    (L_TOT / ROWS_PB)   // 2500
#define THREADS    128                 // 4 warps = 4 n-strips
#define CHUNK_ROWS 32                  // 2 m16-tiles per chunk
#define NCHUNK     (ROWS_PB / CHUNK_ROWS)   // 15

// fp16 staged rows: 64 halfs payload, permuted by pair so lane q's 8 pairs
// (pair p == q mod 4) are contiguous: pair p -> 4B-word (p&3)*8 + (p>>2).
// Row padded to 144B (36 words): LDS.128 phases conflict-free.
#define RSB        144
#define BUF_BYTES  (CHUNK_ROWS * RSB)             // 4608
#define F_STRIDE   136
#define FT_FLOATS  (SEG_PB * F_STRIDE)            // 2176 (single plane)
#define SMEM_BYTES (2 * BUF_BYTES + FT_FLOATS * 4)  // 17920 B

__device__ __forceinline__ uint32_t pack_h2(float lo, float hi) {
    uint32_t r;
    asm("cvt.rn.f16x2.f32 %0, %1, %2;" : "=r"(r) : "f"(hi), "f"(lo));
    return r;
}

__device__ __forceinline__ void mma_f16(float c[4],
                                        uint32_t a0, uint32_t a1, uint32_t a2, uint32_t a3,
                                        uint32_t b0, uint32_t b1) {
    asm volatile(
        "mma.sync.aligned.m16n8k16.row.col.f32.f16.f16.f32 "
        "{%0,%1,%2,%3}, {%4,%5,%6,%7}, {%8,%9}, {%0,%1,%2,%3};"
        : "+f"(c[0]), "+f"(c[1]), "+f"(c[2]), "+f"(c[3])
        : "r"(a0), "r"(a1), "r"(a2), "r"(a3), "r"(b0), "r"(b1));
}

// Reduce-scatter of 8 values across the 8-lane group {lane ^ 4,8,16}.
// Lane ends with the total for value index j = 4*b2 + 2*b3 + b4. 7 shfl + 7 add.
__device__ __forceinline__ float rs8(const float v[8], int lane) {
    float w[4];
    #pragma unroll
    for (int i = 0; i < 4; ++i) {
        float give = (lane & 4) ? v[i] : v[4 + i];
        float keep = (lane & 4) ? v[4 + i] : v[i];
        w[i] = keep + __shfl_xor_sync(0xffffffffu, give, 4);
    }
    float u[2];
    #pragma unroll
    for (int i = 0; i < 2; ++i) {
        float give = (lane & 8) ? w[i] : w[2 + i];
        float keep = (lane & 8) ? w[2 + i] : w[i];
        u[i] = keep + __shfl_xor_sync(0xffffffffu, give, 8);
    }
    float give = (lane & 16) ? u[0] : u[1];
    float keep = (lane & 16) ? u[1] : u[0];
    return keep + __shfl_xor_sync(0xffffffffu, give, 16);
}

// One 16-row m-tile: 4 LDS.128 -> 16 mma(k16) -> relu -> pooled accumulate.
__device__ __forceinline__ void do_tile(const char* __restrict__ xb, int ltRow, int rA,
                                        const uint32_t bq[4][4][2],
                                        float* __restrict__ fg,
                                        int lane, int r, int q, int colIdx) {
    float acc[4][4];
    #pragma unroll
    for (int f = 0; f < 4; ++f)
        acc[f][0] = acc[f][1] = acc[f][2] = acc[f][3] = 0.0f;

    const uint4* lo4 = reinterpret_cast<const uint4*>(xb + (ltRow + r) * RSB + q * 32);
    const uint4* hi4 = reinterpret_cast<const uint4*>(xb + (ltRow + r + 8) * RSB + q * 32);
    uint4 L0 = lo4[0], L1 = lo4[1];
    uint4 H0 = hi4[0], H1 = hi4[1];

    #pragma unroll
    for (int f = 0; f < 4; ++f)
        mma_f16(acc[f], L0.x, H0.x, L0.y, H0.y, bq[0][f][0], bq[0][f][1]);
    #pragma unroll
    for (int f = 0; f < 4; ++f)
        mma_f16(acc[f], L0.z, H0.z, L0.w, H0.w, bq[1][f][0], bq[1][f][1]);
    #pragma unroll
    for (int f = 0; f < 4; ++f)
        mma_f16(acc[f], L1.x, H1.x, L1.y, H1.y, bq[2][f][0], bq[2][f][1]);
    #pragma unroll
    for (int f = 0; f < 4; ++f)
        mma_f16(acc[f], L1.z, H1.z, L1.w, H1.w, bq[3][f][0], bq[3][f][1]);

    // relu
    #pragma unroll
    for (int f = 0; f < 4; ++f) {
        acc[f][0] = fmaxf(acc[f][0], 0.0f);
        acc[f][1] = fmaxf(acc[f][1], 0.0f);
        acc[f][2] = fmaxf(acc[f][2], 0.0f);
        acc[f][3] = fmaxf(acc[f][3], 0.0f);
    }

    const int sLo = rA / JWIN;
    const int sHi = (rA + 15) / JWIN;

    if (sLo == sHi) {
        float v[8];
        #pragma unroll
        for (int f = 0; f < 4; ++f) {
            v[2 * f]     = acc[f][0] + acc[f][2];
            v[2 * f + 1] = acc[f][1] + acc[f][3];
        }
        fg[sLo * F_STRIDE + colIdx] += rs8(v, lane);
    } else {
        const int b = sHi * JWIN - rA;
        const bool pL = (r < b);
        const bool pH = (r + 8 < b);
        float vlo[8], vhi[8];
        #pragma unroll
        for (int f = 0; f < 4; ++f) {
            float l0 = pL ? acc[f][0] : 0.0f;
            float l1 = pL ? acc[f][1] : 0.0f;
            float l2 = pH ? acc[f][2] : 0.0f;
            float l3 = pH ? acc[f][3] : 0.0f;
            vlo[2 * f]     = l0 + l2;
            vlo[2 * f + 1] = l1 + l3;
            vhi[2 * f]     = (acc[f][0] + acc[f][2]) - vlo[2 * f];
            vhi[2 * f + 1] = (acc[f][1] + acc[f][3]) - vlo[2 * f + 1];
        }
        float slo = rs8(vlo, lane);
        float shi = rs8(vhi, lane);
        fg[sLo * F_STRIDE + colIdx] += slo;
        fg[sHi * F_STRIDE + colIdx] += shi;
    }
}

__global__ __launch_bounds__(THREADS, 5)
void classifier_kernel(const float* __restrict__ x,
                       const float* __restrict__ Wloc,
                       const float* __restrict__ W,
                       float* __restrict__ out) {
    extern __shared__ char smem[];
    char* bufs   = smem;                          // 2 x [32 rows][144B] fp16 perm
    float* feats = reinterpret_cast<float*>(smem + 2 * BUF_BYTES);  // [16][136]

    const int tid = threadIdx.x;
    const int blk = blockIdx.x;
    const long rowBase = (long)blk * ROWS_PB;

    const int lane = tid & 31;
    const int wid  = tid >> 5;
    const int nb   = wid * 32;           // this warp's 32-col n-strip
    const int r    = lane >> 2;
    const int q    = lane & 3;

    const int colIdx = nb
        + (2 * ((lane >> 2) & 1) + ((lane >> 3) & 1)) * 8
        + 2 * q
        + ((lane >> 4) & 1);

    // staging: wave w covers rows [16w,16w+16); element i = j*128 + tid
    //  -> row 16w + j*8 + (tid>>4), float4-col tid&15
    const int pr0 = tid >> 4;            // base row within wave (0..7); j adds 8
    const int wc4 = tid & 15;
    const int w0 = 16 * (wc4 & 1) + (wc4 >> 1);   // word slot; 2nd pair at w0+8

    // ---- prologue: LDG wave0 of chunk 0 (start DRAM immediately) ----
    float4 pf[2];
    {
        const float4* s4 = reinterpret_cast<const float4*>(x + rowBase * D_IN);
        pf[0] = s4[tid];
        pf[1] = s4[THREADS + tid];
    }

    // zero feats (overlaps LDG)
    for (int i = tid; i < FT_FLOATS; i += THREADS) feats[i] = 0.0f;

    // B frags fp16 (m16n8k16, col): n = nb + 8f + r; b0 k=16ks+2q(+1), b1 +8
    uint32_t bq[4][4][2];
    {
        const float* wb = Wloc + (nb + r) * D_IN + 2 * q;
        #pragma unroll
        for (int ks = 0; ks < 4; ++ks) {
            #pragma unroll
            for (int f = 0; f < 4; ++f) {
                float2 v0 = __ldg(reinterpret_cast<const float2*>(wb + f * 8 * D_IN + ks * 16));
                float2 v1 = __ldg(reinterpret_cast<const float2*>(wb + f * 8 * D_IN + ks * 16 + 8));
                bq[ks][f][0] = pack_h2(v0.x, v0.y);
                bq[ks][f][1] = pack_h2(v1.x, v1.y);
            }
        }
    }

    // stage wave0 of chunk 0; then LDG+stage wave1 of chunk 0
    #pragma unroll
    for (int j = 0; j < 2; ++j) {
        uint32_t* rowp = reinterpret_cast<uint32_t*>(bufs + (pr0 + j * 8) * RSB);
        rowp[w0]     = pack_h2(pf[j].x, pf[j].y);
        rowp[w0 + 8] = pack_h2(pf[j].z, pf[j].w);
    }
    {
        const float4* s4 = reinterpret_cast<const float4*>(x + (rowBase + 16) * D_IN);
        pf[0] = s4[tid];
        pf[1] = s4[THREADS + tid];
    }
    #pragma unroll
    for (int j = 0; j < 2; ++j) {
        uint32_t* rowp = reinterpret_cast<uint32_t*>(bufs + (16 + pr0 + j * 8) * RSB);
        rowp[w0]     = pack_h2(pf[j].x, pf[j].y);
        rowp[w0 + 8] = pack_h2(pf[j].z, pf[j].w);
    }
    __syncthreads();

    // ---- mainloop: 15 chunks; per chunk: LDGw0 tile0 STSw0 LDGw1 tile1 STSw1 bar
    #pragma unroll
    for (int c = 0; c < NCHUNK; ++c) {
        const char* xb = bufs + (c & 1) * BUF_BYTES;
        char* nx = bufs + ((c + 1) & 1) * BUF_BYTES;

        // LDG wave0 of chunk c+1
        if (c + 1 < NCHUNK) {
            const float4* s4 = reinterpret_cast<const float4*>(
                x + (rowBase + (long)(c + 1) * CHUNK_ROWS) * D_IN);
            pf[0] = s4[tid];
            pf[1] = s4[THREADS + tid];
        }

        // tile 0 (rows 32c .. 32c+15) — covers LDG wave0 latency
        do_tile(xb, 0, c * CHUNK_ROWS, bq, feats, lane, r, q, colIdx);

        // STS wave0 of chunk c+1 (target buffer free since barrier of chunk c-1)
        if (c + 1 < NCHUNK) {
            #pragma unroll
            for (int j = 0; j < 2; ++j) {
                uint32_t* rowp = reinterpret_cast<uint32_t*>(nx + (pr0 + j * 8) * RSB);
                rowp[w0]     = pack_h2(pf[j].x, pf[j].y);
                rowp[w0 + 8] = pack_h2(pf[j].z, pf[j].w);
            }
            // LDG wave1 of chunk c+1
            const float4* s4 = reinterpret_cast<const float4*>(
                x + (rowBase + (long)(c + 1) * CHUNK_ROWS + 16) * D_IN);
            pf[0] = s4[tid];
            pf[1] = s4[THREADS + tid];
        }

        // tile 1 (rows 32c+16 .. 32c+31) — same warp, same feats cols: no race
        do_tile(xb, 16, c * CHUNK_ROWS + 16, bq, feats, lane, r, q, colIdx);

        // STS wave1 of chunk c+1
        if (c + 1 < NCHUNK) {
            #pragma unroll
            for (int j = 0; j < 2; ++j) {
                uint32_t* rowp = reinterpret_cast<uint32_t*>(nx + (16 + pr0 + j * 8) * RSB);
                rowp[w0]     = pack_h2(pf[j].x, pf[j].y);
                rowp[w0 + 8] = pack_h2(pf[j].z, pf[j].w);
            }
        }
        __syncthreads();
    }

    // ---- fused classifier: out[s][cc] = (1/30) * sum_e feats[s][e] * W[cc][e] ----
    for (int t = tid; t < SEG_PB * N_CLS; t += THREADS) {
        const int s  = t / N_CLS;
        const int cc = t - s * N_CLS;
        const float4* fr = reinterpret_cast<const float4*>(feats + s * F_STRIDE);
        const float4* wr = reinterpret_cast<const float4*>(W + cc * D_ENC);
        float sum = 0.0f;
        #pragma unroll
        for (int e4 = 0; e4 < D_ENC / 4; ++e4) {
            float4 a = fr[e4];
            float4 w4 = __ldg(&wr[e4]);
            sum += a.x * w4.x + a.y * w4.y + a.z * w4.z + a.w * w4.w;
        }
        out[((long)blk * SEG_PB + s) * N_CLS + cc] = sum * (1.0f / (float)JWIN);
    }
}

extern "C" void kernel_launch(void* const* d_in, const int* in_sizes, int n_in,
                              void* d_out, int out_size) {
    const float* x    = (const float*)d_in[0];   // [1200000, 64]
    const float* Wloc = (const float*)d_in[1];   // [128, 64]
    const float* W    = (const float*)d_in[2];   // [10, 128]
    float* out = (float*)d_out;                  // [40000, 10]

    cudaFuncSetAttribute(classifier_kernel,
                         cudaFuncAttributeMaxDynamicSharedMemorySize, SMEM_BYTES);
    classifier_kernel<<<NBLOCKS, THREADS, SMEM_BYTES>>>(x, Wloc, W, out);
}